// round 1
// baseline (speedup 1.0000x reference)
#include <cuda_runtime.h>
#include <cstdint>

// ---------------- problem constants ----------------
#define BW    1024
#define SEQ   144
#define CH    512
#define NH    16
#define DH    32
#define NWIN  64
#define MROWS (BW*SEQ)          // 147456
#define LOG100 4.6051701859880913680f

// ---------------- scratch (device globals; no cudaMalloc allowed) ----------
__device__ float g_qkv[(size_t)MROWS * 1536];   // q|k|v concatenated per row
__device__ float g_att[(size_t)MROWS * 512];    // attention output (Bw,L,C)

// ============================================================
// GEMM: C[m, z*512 + n] = sum_k A[m,k] * B_z[n,k] + bias_z[n]
// tf32 mma.sync m16n8k8, tiles 128x128x32, 256 threads (8 warps, 2x4)
// grid.x = 4 * nz (x fastest -> all N/z tiles of one M band share A in L2)
// ============================================================
#define APAD 36   // smem row stride in 4B words: 36 % 32 == 4 -> conflict-free frags

__device__ __forceinline__ uint32_t f2tf32(float f) {
    uint32_t u;
    asm("cvt.rna.tf32.f32 %0, %1;" : "=r"(u) : "f"(f));
    return u;
}

__device__ __forceinline__ void gemm_lds_tiles(const float* __restrict__ Ap,
                                               const float* __restrict__ Bp,
                                               int tid, int K,
                                               float4* a_st, float4* b_st) {
#pragma unroll
    for (int i = 0; i < 4; i++) {
        int idx = tid + i * 256;
        int r = idx >> 3, c = (idx & 7) * 4;
        a_st[i] = *(const float4*)(Ap + (size_t)r * K + c);
        b_st[i] = *(const float4*)(Bp + (size_t)r * K + c);
    }
}

__device__ __forceinline__ void gemm_sts_tiles(uint32_t* __restrict__ As,
                                               uint32_t* __restrict__ Bs,
                                               int tid,
                                               const float4* a_st, const float4* b_st) {
#pragma unroll
    for (int i = 0; i < 4; i++) {
        int idx = tid + i * 256;
        int r = idx >> 3, c = (idx & 7) * 4;
        uint32_t* da = As + r * APAD + c;
        da[0] = f2tf32(a_st[i].x); da[1] = f2tf32(a_st[i].y);
        da[2] = f2tf32(a_st[i].z); da[3] = f2tf32(a_st[i].w);
        uint32_t* db = Bs + r * APAD + c;
        db[0] = f2tf32(b_st[i].x); db[1] = f2tf32(b_st[i].y);
        db[2] = f2tf32(b_st[i].z); db[3] = f2tf32(b_st[i].w);
    }
}

__global__ void __launch_bounds__(256, 2)
gemm_tf32_kernel(const float* __restrict__ A,
                 const float* __restrict__ B0, const float* __restrict__ B1,
                 const float* __restrict__ B2,
                 const float* __restrict__ bias0, const float* __restrict__ bias1,
                 const float* __restrict__ bias2,
                 float* __restrict__ Cout, int ldc, int K)
{
    const int z  = blockIdx.x >> 2;
    const int nb = blockIdx.x & 3;
    const float* B    = (z == 0) ? B0 : (z == 1 ? B1 : B2);
    const float* bias = (z == 0) ? bias0 : (z == 1 ? bias1 : bias2);

    const int m0 = blockIdx.y * 128;
    const int n0 = nb * 128;

    extern __shared__ uint32_t smem_u[];
    uint32_t* As = smem_u;                       // [2][128][APAD]
    uint32_t* Bs = smem_u + 2 * 128 * APAD;      // [2][128][APAD]

    const int tid  = threadIdx.x;
    const int warp = tid >> 5, lane = tid & 31;
    const int wm = warp & 1;        // 0..1 -> 64 rows
    const int wn = warp >> 1;       // 0..3 -> 32 cols
    const int g  = lane >> 2, tg = lane & 3;

    float acc[4][4][4];
#pragma unroll
    for (int i = 0; i < 4; i++)
#pragma unroll
        for (int j = 0; j < 4; j++)
#pragma unroll
            for (int r = 0; r < 4; r++) acc[i][j][r] = 0.f;

    float4 a_st[4], b_st[4];
    gemm_lds_tiles(A + (size_t)m0 * K, B + (size_t)n0 * K, tid, K, a_st, b_st);
    gemm_sts_tiles(As, Bs, tid, a_st, b_st);
    __syncthreads();

    const int nk = K / 32;
    int buf = 0;
#pragma unroll 1
    for (int kt = 0; kt < nk; kt++) {
        if (kt + 1 < nk) {
            gemm_lds_tiles(A + (size_t)m0 * K + (kt + 1) * 32,
                           B + (size_t)n0 * K + (kt + 1) * 32, tid, K, a_st, b_st);
        }
        const uint32_t* Ab = As + buf * 128 * APAD;
        const uint32_t* Bb = Bs + buf * 128 * APAD;
#pragma unroll
        for (int ks = 0; ks < 4; ks++) {
            uint32_t af[4][4], bf[4][2];
#pragma unroll
            for (int mi = 0; mi < 4; mi++) {
                const uint32_t* p = Ab + (wm * 64 + mi * 16 + g) * APAD + ks * 8 + tg;
                af[mi][0] = p[0];
                af[mi][2] = p[4];
                const uint32_t* p2 = p + 8 * APAD;
                af[mi][1] = p2[0];
                af[mi][3] = p2[4];
            }
#pragma unroll
            for (int ni = 0; ni < 4; ni++) {
                const uint32_t* p = Bb + (wn * 32 + ni * 8 + g) * APAD + ks * 8 + tg;
                bf[ni][0] = p[0];
                bf[ni][1] = p[4];
            }
#pragma unroll
            for (int mi = 0; mi < 4; mi++)
#pragma unroll
                for (int ni = 0; ni < 4; ni++) {
                    asm volatile(
                        "mma.sync.aligned.m16n8k8.row.col.f32.tf32.tf32.f32 "
                        "{%0,%1,%2,%3}, {%4,%5,%6,%7}, {%8,%9}, {%0,%1,%2,%3};\n"
                        : "+f"(acc[mi][ni][0]), "+f"(acc[mi][ni][1]),
                          "+f"(acc[mi][ni][2]), "+f"(acc[mi][ni][3])
                        : "r"(af[mi][0]), "r"(af[mi][1]), "r"(af[mi][2]), "r"(af[mi][3]),
                          "r"(bf[ni][0]), "r"(bf[ni][1]));
                }
        }
        if (kt + 1 < nk)
            gemm_sts_tiles(As + (buf ^ 1) * 128 * APAD, Bs + (buf ^ 1) * 128 * APAD,
                           tid, a_st, b_st);
        buf ^= 1;
        __syncthreads();
    }

    // epilogue: c0 (g,2tg) c1 (g,2tg+1) c2 (g+8,2tg) c3 (g+8,2tg+1)
#pragma unroll
    for (int mi = 0; mi < 4; mi++) {
        int row = m0 + wm * 64 + mi * 16 + g;
#pragma unroll
        for (int ni = 0; ni < 4; ni++) {
            int ncol = n0 + wn * 32 + ni * 8 + 2 * tg;      // 0..511 within matrix z
            int gcol = z * 512 + ncol;
            float b0 = bias[ncol], b1 = bias[ncol + 1];
            float2 v0 = make_float2(acc[mi][ni][0] + b0, acc[mi][ni][1] + b1);
            float2 v1 = make_float2(acc[mi][ni][2] + b0, acc[mi][ni][3] + b1);
            *(float2*)(Cout + (size_t)row * ldc + gcol) = v0;
            *(float2*)(Cout + (size_t)(row + 8) * ldc + gcol) = v1;
        }
    }
}

// ============================================================
// Attention: one CTA per (b,h). K/V in SMEM, q/k L2-normalized at load,
// logit scale folded into q. 48 q-rows per chunk, exact softmax, PV.
// ============================================================
#define KPAD 33
#define SPAD 145
// smem floats: ks 144*33 + vs 144*33 + qs 48*33 + ss 48*145 = 18048 (72192 B)
#define ATT_SMEM_FLOATS (144*KPAD + 144*KPAD + 48*KPAD + 48*SPAD)

__global__ void __launch_bounds__(256)
attn_kernel(const float* __restrict__ mask,
            const float* __restrict__ logit_scale,
            float* __restrict__ attout)
{
    const int bh = blockIdx.x;
    const int b = bh >> 4;
    const int h = bh & 15;
    const int w = b & (NWIN - 1);

    const int tid = threadIdx.x;
    const int warp = tid >> 5, lane = tid & 31;

    extern __shared__ float sm[];
    float* ks = sm;                       // [144][33]
    float* vs = ks + 144 * KPAD;          // [144][33]
    float* qs = vs + 144 * KPAD;          // [48][33]
    float* ss = qs + 48 * KPAD;           // [48][145]

    const float scale = expf(fminf(logit_scale[h], LOG100));

    const float* qbase = g_qkv + (size_t)(b * SEQ) * 1536 + h * 32;
    const float* kbase = qbase + 512;
    const float* vbase = qbase + 1024;

    // ---- load K (normalized) and V ----
#pragma unroll
    for (int rr = 0; rr < 18; rr++) {
        int r = warp * 18 + rr;
        float kv = kbase[(size_t)r * 1536 + lane];
        float sq = kv * kv;
#pragma unroll
        for (int off = 16; off > 0; off >>= 1)
            sq += __shfl_xor_sync(0xffffffffu, sq, off);
        float inv = 1.f / fmaxf(sqrtf(sq), 1e-12f);
        ks[r * KPAD + lane] = kv * inv;
        vs[r * KPAD + lane] = vbase[(size_t)r * 1536 + lane];
    }
    __syncthreads();

    const float NEG_INF = __int_as_float(0xff800000);

    for (int cb = 0; cb < 3; cb++) {
        const int qr0 = cb * 48;

        // ---- load q chunk (normalized, scaled) ----
#pragma unroll
        for (int rr = 0; rr < 6; rr++) {
            int r = warp * 6 + rr;
            float qv = qbase[(size_t)(qr0 + r) * 1536 + lane];
            float sq = qv * qv;
#pragma unroll
            for (int off = 16; off > 0; off >>= 1)
                sq += __shfl_xor_sync(0xffffffffu, sq, off);
            float inv = scale / fmaxf(sqrtf(sq), 1e-12f);
            qs[r * KPAD + lane] = qv * inv;
        }
        __syncthreads();

        // ---- S = q @ k^T + mask : thread (tx,ty) computes 3 rows x 9 cols ----
        {
            const int tx = tid & 15, ty = tid >> 4;
            float a[3][9];
#pragma unroll
            for (int r = 0; r < 3; r++)
#pragma unroll
                for (int c = 0; c < 9; c++) a[r][c] = 0.f;

#pragma unroll 8
            for (int d = 0; d < 32; d++) {
                float qv[3], kv[9];
#pragma unroll
                for (int r = 0; r < 3; r++) qv[r] = qs[(ty * 3 + r) * KPAD + d];
#pragma unroll
                for (int c = 0; c < 9; c++) kv[c] = ks[(tx * 9 + c) * KPAD + d];
#pragma unroll
                for (int r = 0; r < 3; r++)
#pragma unroll
                    for (int c = 0; c < 9; c++) a[r][c] = fmaf(qv[r], kv[c], a[r][c]);
            }
            const float* mbase = mask + ((size_t)w * SEQ + qr0 + ty * 3) * SEQ + tx * 9;
#pragma unroll
            for (int r = 0; r < 3; r++)
#pragma unroll
                for (int c = 0; c < 9; c++)
                    ss[(ty * 3 + r) * SPAD + tx * 9 + c] = a[r][c] + mbase[(size_t)r * SEQ + c];
        }
        __syncthreads();

        // ---- softmax per row (warp handles 6 rows) ----
#pragma unroll
        for (int rr = 0; rr < 6; rr++) {
            int r = warp * 6 + rr;
            float* row = ss + r * SPAD;
            float v0 = row[lane];
            float v1 = row[lane + 32];
            float v2 = row[lane + 64];
            float v3 = row[lane + 96];
            float v4 = (lane < 16) ? row[lane + 128] : NEG_INF;
            float mx = fmaxf(fmaxf(fmaxf(v0, v1), fmaxf(v2, v3)), v4);
#pragma unroll
            for (int off = 16; off > 0; off >>= 1)
                mx = fmaxf(mx, __shfl_xor_sync(0xffffffffu, mx, off));
            float e0 = __expf(v0 - mx);
            float e1 = __expf(v1 - mx);
            float e2 = __expf(v2 - mx);
            float e3 = __expf(v3 - mx);
            float e4 = (lane < 16) ? __expf(v4 - mx) : 0.f;
            float s = e0 + e1 + e2 + e3 + e4;
#pragma unroll
            for (int off = 16; off > 0; off >>= 1)
                s += __shfl_xor_sync(0xffffffffu, s, off);
            float invs = 1.f / s;
            row[lane]      = e0 * invs;
            row[lane + 32] = e1 * invs;
            row[lane + 64] = e2 * invs;
            row[lane + 96] = e3 * invs;
            if (lane < 16) row[lane + 128] = e4 * invs;
        }
        __syncthreads();

        // ---- O = P @ V : warp owns 6 rows, lane owns one d ----
        {
            float o[6];
#pragma unroll
            for (int i = 0; i < 6; i++) o[i] = 0.f;
#pragma unroll 4
            for (int j = 0; j < 144; j++) {
                float vv = vs[j * KPAD + lane];
#pragma unroll
                for (int i = 0; i < 6; i++)
                    o[i] = fmaf(ss[(warp * 6 + i) * SPAD + j], vv, o[i]);
            }
#pragma unroll
            for (int i = 0; i < 6; i++)
                attout[(size_t)(b * SEQ + qr0 + warp * 6 + i) * 512 + h * 32 + lane] = o[i];
        }
        __syncthreads();
    }
}

// ============================================================
// launch
// ============================================================
extern "C" void kernel_launch(void* const* d_in, const int* in_sizes, int n_in,
                              void* d_out, int out_size)
{
    (void)in_sizes; (void)n_in; (void)out_size;
    const float* x    = (const float*)d_in[0];
    const float* mask = (const float*)d_in[1];
    const float* Wq   = (const float*)d_in[2];
    const float* bq   = (const float*)d_in[3];
    const float* Wk   = (const float*)d_in[4];
    const float* bk   = (const float*)d_in[5];
    const float* Wv   = (const float*)d_in[6];
    const float* bv   = (const float*)d_in[7];
    const float* Wp   = (const float*)d_in[8];
    const float* bp   = (const float*)d_in[9];
    const float* ls   = (const float*)d_in[10];
    float* out = (float*)d_out;

    void* qkv_p = nullptr;
    void* att_p = nullptr;
    cudaGetSymbolAddress(&qkv_p, g_qkv);
    cudaGetSymbolAddress(&att_p, g_att);
    float* qkv = (float*)qkv_p;
    float* att = (float*)att_p;

    const int gemm_smem = 2 * 2 * 128 * APAD * 4;          // 73728 B
    const int att_smem  = ATT_SMEM_FLOATS * 4;             // 72192 B
    cudaFuncSetAttribute(gemm_tf32_kernel,
                         cudaFuncAttributeMaxDynamicSharedMemorySize, gemm_smem);
    cudaFuncSetAttribute(attn_kernel,
                         cudaFuncAttributeMaxDynamicSharedMemorySize, att_smem);

    // QKV projections (z folded into grid.x: 12 = 4 N-tiles * 3 matrices)
    dim3 gq(12, MROWS / 128, 1);
    gemm_tf32_kernel<<<gq, 256, gemm_smem>>>(x, Wq, Wk, Wv, bq, bk, bv,
                                             qkv, 1536, CH);

    // attention
    attn_kernel<<<BW * NH, 256, att_smem>>>(mask, ls, att);

    // output projection
    dim3 gp(4, MROWS / 128, 1);
    gemm_tf32_kernel<<<gp, 256, gemm_smem>>>(att, Wp, Wp, Wp, bp, bp, bp,
                                             out, 512, CH);
}